// round 7
// baseline (speedup 1.0000x reference)
#include <cuda_runtime.h>

// ---------------- problem constants ----------------
#define C_CLASSES 8192
#define B_ROWS    256
#define N_ROWS    1280                 // B + M*B
#define CPB       8                    // classes per block in KB
#define MAXP      64                   // per-class positive cap (Poisson(12.8))
#define SSTRIDE   1281                 // 1280 + 1 pad

#define NI        (B_ROWS * C_CLASSES) // 2097152 interclass elements
#define LG_BINS   18
#define BINS      (1 << LG_BINS)       // 262144
#define KEY_SHIFT (32 - LG_BINS)       // 14
#define MAXPOS    32768                // total interclass positives ~21k
#define SALT      0x9E00000000ULL      // disjoint RNG stream for interclass

// ---------------- scratch (device globals; no allocation allowed) ----------------
__device__ float    g_prec[C_CLASSES];
__device__ int      g_present[C_CLASSES];

__device__ unsigned g_ikeys[NI];            // interclass order-keys
__device__ unsigned g_plist[MAXPOS];        // unordered positive keys
__device__ int      g_pcount;
__device__ int      g_phist[BINS];          // positive count per bin
__device__ int      g_pexcl[BINS + 1];      // exclusive prefix (+ sentinel = m)
__device__ int      g_pcursor[BINS];
__device__ unsigned g_pkeys[MAXPOS];        // positive keys grouped by bin
__device__ int      g_gapall[MAXPOS + 64];  // #elements with exactly j positives above
__device__ int      g_mtotal;

// ---------------- RNG: splitmix64 -> popc-normal (no MUFU) ----------------
__device__ __forceinline__ float abs_normal(unsigned long long idx) {
    unsigned long long z = idx + 0x9E3779B97F4A7C15ULL;
    z = (z ^ (z >> 30)) * 0xBF58476D1CE4E5B9ULL;
    z = (z ^ (z >> 27)) * 0x94D049BB133111EBULL;
    z ^= (z >> 31);
    unsigned lo = (unsigned)z;
    unsigned hi = (unsigned)(z >> 32);
    float b = (float)(__popc(lo) - 16);
    float u = fmaf((float)(hi >> 8), 5.9604645e-08f, -0.5f);   // [-0.5, 0.5)
    return fabsf((b + u) * 0.35172433f);                        // 1/sqrt(8+1/12)
}

__device__ __forceinline__ unsigned order_key(float v) {
    unsigned u = __float_as_uint(v);
    return (u & 0x80000000u) ? ~u : (u | 0x80000000u);
}

__device__ __forceinline__ int warp_sum(int v) {
    #pragma unroll
    for (int off = 16; off; off >>= 1) v += __shfl_xor_sync(0xffffffffu, v, off);
    return v;
}

// ---------------- K0: zero counters ----------------
__global__ __launch_bounds__(256) void k0_zero() {
    int i = blockIdx.x * 256 + threadIdx.x;
    if (i < BINS) g_phist[i] = 0;
    if (i < MAXPOS + 64) g_gapall[i] = 0;
    if (i == 0) g_pcount = 0;
}

// ---------------- KB: fused perturb + cross-term ranking + interclass emit ----------------
extern __shared__ float kb_smem[];

__global__ __launch_bounds__(256) void kb_fused(
    const float* __restrict__ outp, const float* __restrict__ tgt,
    const float* __restrict__ soutp, const float* __restrict__ stgt)
{
    float* sval = kb_smem;                    // [CPB][SSTRIDE]
    float* spos = sval + CPB * SSTRIDE;       // [CPB][MAXP]
    __shared__ int pcnt[CPB];
    __shared__ unsigned s_ilist[128];
    __shared__ int s_icnt;
    __shared__ int s_ibase;

    int tid = threadIdx.x;
    int c0 = blockIdx.x * CPB;
    if (tid < CPB) pcnt[tid] = 0;
    if (tid == 0) { s_icnt = 0; s_ibase = 0; }
    __syncthreads();

    // ---- Phase 1: stream all rows of this block's 8 classes ----
    #pragma unroll 4
    for (int it = 0; it < (N_ROWS * CPB) / 256; it++) {    // 40 iterations
        int idx = it * 256 + tid;
        int r = idx >> 3;
        int c = idx & 7;
        int col = c0 + c;
        float sc, t;
        if (r < B_ROWS) {
            size_t o = (size_t)r * C_CLASSES + col;
            sc = outp[o]; t = tgt[o];
        } else {
            size_t o = (size_t)(r - B_ROWS) * C_CLASSES + col;
            sc = soutp[o]; t = stgt[o];
        }
        unsigned long long gi = (unsigned long long)r * C_CLASSES + (unsigned long long)col;
        float an = abs_normal(gi);
        bool pos = (t > 0.5f);
        float v = pos ? (sc - 0.01f * an) : (sc + 0.01f * an);
        sval[c * SSTRIDE + r] = v;
        if (pos) {
            int d = atomicAdd(&pcnt[c], 1);
            if (d < MAXP) spos[c * MAXP + d] = v;
        }
        if (r < B_ROWS) {              // interclass stream
            float an2 = abs_normal(SALT + gi);
            float iv = pos ? (sc - 0.01f * an2) : (sc + 0.01f * an2);
            unsigned key = order_key(iv);
            g_ikeys[r * C_CLASSES + col] = key;
            if (pos) {
                atomicAdd(&g_phist[key >> KEY_SHIFT], 1);
                int d2 = atomicAdd(&s_icnt, 1);
                if (d2 < 128) s_ilist[d2] = key;
            }
        }
    }
    __syncthreads();

    // one global atomic per block to reserve positive-list space
    int icnt = (s_icnt < 128) ? s_icnt : 128;
    if (tid == 0 && icnt > 0) s_ibase = atomicAdd(&g_pcount, icnt);
    __syncthreads();
    if (tid < icnt) {
        int dst = s_ibase + tid;
        if (dst < MAXPOS) g_plist[dst] = s_ilist[tid];
    }

    // ---- Phase 2: warp w ranks class c0+w ----
    int w = tid >> 5, lane = tid & 31;
    float v[N_ROWS / 32];
    #pragma unroll
    for (int j = 0; j < N_ROWS / 32; j++)
        v[j] = sval[w * SSTRIDE + j * 32 + lane];

    int m = pcnt[w];
    int ms = (m < MAXP) ? m : MAXP;
    double sum = 0.0;
    for (int k = 0; k < ms; k++) {
        float p = spos[w * MAXP + k];       // broadcast
        int cnt = 0;
        #pragma unroll
        for (int j = 0; j < N_ROWS / 32; j++) cnt += (v[j] > p);
        int r = warp_sum(cnt) + 1;          // global descending rank
        int s = 1;                          // rank among positives
        for (int jj = 0; jj < ms; jj++) s += (spos[w * MAXP + jj] > p);
        sum += (double)((float)s / (float)r);
    }
    if (lane == 0) {
        g_prec[c0 + w]    = (float)(sum / ((double)m + 1e-5));
        g_present[c0 + w] = (m > 0) ? 1 : 0;
    }
}

// ---------------- KPREP: single-block hist scan + cursor init + positive binning ----------------
#define KP_PER_T (BINS / 1024)    // 256 bins per thread
__global__ __launch_bounds__(1024) void kprep() {
    __shared__ int warp_tot[32];
    int t = threadIdx.x;
    int lane = t & 31, wid = t >> 5;
    int base = t * KP_PER_T;

    // pass 1: per-thread sum
    int s = 0;
    for (int j = 0; j < KP_PER_T; j += 4) {
        int4 q = *(const int4*)&g_phist[base + j];
        s += q.x + q.y + q.z + q.w;
    }
    // block exclusive scan of per-thread sums
    int si = s;
    #pragma unroll
    for (int off = 1; off < 32; off <<= 1) {
        int n = __shfl_up_sync(0xffffffffu, si, off);
        if (lane >= off) si += n;
    }
    if (lane == 31) warp_tot[wid] = si;
    __syncthreads();
    if (wid == 0) {
        int w = warp_tot[lane];
        #pragma unroll
        for (int off = 1; off < 32; off <<= 1) {
            int n = __shfl_up_sync(0xffffffffu, w, off);
            if (lane >= off) w += n;
        }
        warp_tot[lane] = w;
    }
    __syncthreads();
    int run = (wid > 0 ? warp_tot[wid - 1] : 0) + si - s;

    // pass 2: write exclusive offsets + cursors
    for (int j = 0; j < KP_PER_T; j += 4) {
        int4 q = *(const int4*)&g_phist[base + j];
        int4 e;
        e.x = run; e.y = run + q.x; e.z = e.y + q.y; e.w = e.z + q.z;
        *(int4*)&g_pexcl[base + j]   = e;
        *(int4*)&g_pcursor[base + j] = e;
        run = e.w + q.w;
    }
    if (t == 1023) { g_pexcl[BINS] = run; g_mtotal = run; }
    __threadfence();
    __syncthreads();

    // bin the positive keys
    int n = g_pcount;
    if (n > MAXPOS) n = MAXPOS;
    for (int i = t; i < n; i += 1024) {
        unsigned key = g_plist[i];
        int d = atomicAdd(&g_pcursor[key >> KEY_SHIFT], 1);
        g_pkeys[d] = key;
    }
}

// ---------------- KC: per-element gap counting (all elements -> gapall) ----------------
__global__ __launch_bounds__(256) void kc_gaps() {
    int gt = blockIdx.x * 256 + threadIdx.x;
    uint4 k4 = ((const uint4*)g_ikeys)[gt];
    int m = g_mtotal;
    unsigned key[4] = {k4.x, k4.y, k4.z, k4.w};
    #pragma unroll
    for (int u = 0; u < 4; u++) {
        int b  = key[u] >> KEY_SHIFT;
        int e0 = g_pexcl[b];
        int e1 = g_pexcl[b + 1];
        int c = 0;
        for (int t = e0; t < e1; t++) c += (g_pkeys[t] > key[u]);
        int j = (m - e1) + c;               // # positives > this element
        atomicAdd(&g_gapall[j], 1);
    }
}

// ---------------- KS3: gap scan + interclass terms + final combine ----------------
__global__ __launch_bounds__(1024) void ks3_final(float* __restrict__ out, int out_size)
{
    __shared__ int wtot[32];
    __shared__ double wsumd[32];
    __shared__ int wsumi[32];
    int t = threadIdx.x;
    int lane = t & 31, wid = t >> 5;
    int m = g_mtotal;

    int carry = 0;
    double acc = 0.0;
    for (int base = 0; base < m; base += 1024) {
        int i = base + t;
        int g = (i < m) ? (g_gapall[i] - 1) : 0;   // gapneg[j] = gapall[j] - 1
        int si = g;
        #pragma unroll
        for (int off = 1; off < 32; off <<= 1) {
            int n = __shfl_up_sync(0xffffffffu, si, off);
            if (lane >= off) si += n;
        }
        if (lane == 31) wtot[wid] = si;
        __syncthreads();
        if (wid == 0) {
            int w = wtot[lane];
            #pragma unroll
            for (int off = 1; off < 32; off <<= 1) {
                int n = __shfl_up_sync(0xffffffffu, w, off);
                if (lane >= off) w += n;
            }
            wtot[lane] = w;
        }
        __syncthreads();
        int P = (wid > 0 ? wtot[wid - 1] : 0) + si;   // inclusive prefix in chunk
        if (i < m) {
            int r = 1 + i + carry + P;
            acc += (double)((float)(i + 1) / (float)r);
        }
        carry += wtot[31];
        __syncthreads();
    }
    #pragma unroll
    for (int off = 16; off; off >>= 1) acc += __shfl_xor_sync(0xffffffffu, acc, off);
    if (lane == 0) wsumd[wid] = acc;
    __syncthreads();
    double isum = 0.0;
    if (t == 0) {
        #pragma unroll
        for (int i = 0; i < 32; i++) isum += wsumd[i];
    }
    __syncthreads();

    double ps = 0.0; int pr = 0;
    for (int i = t; i < C_CLASSES; i += 1024) { ps += (double)g_prec[i]; pr += g_present[i]; }
    #pragma unroll
    for (int off = 16; off; off >>= 1) {
        ps += __shfl_xor_sync(0xffffffffu, ps, off);
        pr += __shfl_xor_sync(0xffffffffu, pr, off);
    }
    if (lane == 0) { wsumd[wid] = ps; wsumi[wid] = pr; }
    __syncthreads();
    if (t == 0) {
        double pst = 0.0; int prt = 0;
        #pragma unroll
        for (int i = 0; i < 32; i++) { pst += wsumd[i]; prt += wsumi[i]; }
        int denom = (prt > 0) ? prt : 1;
        float cross = 1.0f - (float)(pst / (double)denom);
        float inter = (m > 0) ? (1.0f - (float)(isum / ((double)m + 1e-5))) : 1.0f;
        float loss = 0.5f * cross + 0.5f * inter;
        for (int j = 0; j < out_size; j++) out[j] = loss;
    }
}

// ---------------- launch ----------------
#define KB_SMEM ((CPB * SSTRIDE + CPB * MAXP) * 4)

extern "C" void kernel_launch(void* const* d_in, const int* in_sizes, int n_in,
                              void* d_out, int out_size)
{
    const int SMALL = B_ROWS * C_CLASSES;
    const float* small_p[2] = {nullptr, nullptr};
    const float* big_p[2]   = {nullptr, nullptr};
    int ns = 0, nb = 0;
    for (int i = 0; i < n_in; i++) {
        if (in_sizes[i] == SMALL) { if (ns < 2) small_p[ns++] = (const float*)d_in[i]; }
        else                      { if (nb < 2) big_p[nb++]   = (const float*)d_in[i]; }
    }
    const float* outp  = small_p[0];
    const float* tgt   = small_p[1];
    const float* soutp = big_p[0];
    const float* stgt  = big_p[1];

    k0_zero<<<BINS / 256, 256>>>();
    kb_fused<<<C_CLASSES / CPB, 256, KB_SMEM>>>(outp, tgt, soutp, stgt);
    kprep<<<1, 1024>>>();
    kc_gaps<<<NI / (256 * 4), 256>>>();
    ks3_final<<<1, 1024>>>((float*)d_out, out_size);
}

// round 8
// speedup vs baseline: 1.3220x; 1.3220x over previous
#include <cuda_runtime.h>

// ---------------- problem constants ----------------
#define C_CLASSES 8192
#define B_ROWS    256
#define N_ROWS    1280           // B + M*B
#define NWORDS    40             // N_ROWS/32
#define MAXP      128            // per-class positive cap (cross term)

#define NI        (B_ROWS * C_CLASSES)   // 2097152 interclass elements
#define LG_BINS   18
#define BINS      (1 << LG_BINS)         // 262144
#define KEY_SHIFT (32 - LG_BINS)         // 14
#define CHUNK     64
#define NCHUNK    (BINS / CHUNK)         // 4096
#define MAXPOS    65536
#define NPWORDS   (NI / 32)              // 65536 posbit words

// ---------------- scratch (device globals; no allocation allowed) ----------------
__device__ float    g_tsT[(size_t)C_CLASSES * N_ROWS];
__device__ unsigned g_maskT[C_CLASSES * NWORDS];
__device__ float    g_prec[C_CLASSES];
__device__ int      g_present[C_CLASSES];

__device__ unsigned g_ikeys[NI];          // interclass order-keys
__device__ unsigned g_iposbit[NPWORDS];   // interclass positive bitmask
__device__ int      g_phist[BINS];        // positive count per bin
__device__ int      g_pexcl[BINS];        // exclusive prefix of g_phist
__device__ int      g_pcursor[BINS];
__device__ int      g_pchunksum[NCHUNK];
__device__ unsigned g_pkeys[MAXPOS];      // positive keys grouped by bin
__device__ int      g_gapneg[MAXPOS + 64];
__device__ int      g_mtotal;

// ---------------- RNG: murmur3 finalizer -> popc-normal (cheap, no MUFU) ----------------
// |N(0,1)| ~= |popc(h) - 16 + U(-0.5,0.5)| / sqrt(8 + 1/12)
__device__ __forceinline__ float abs_normal(unsigned idx) {
    unsigned h = idx * 0x9E3779B1u;
    h ^= h >> 16; h *= 0x85EBCA6Bu;
    h ^= h >> 13; h *= 0xC2B2AE35u;
    h ^= h >> 16;
    unsigned h2 = h * 0x2545F491u;                              // decorrelate jitter
    float b = (float)(__popc(h) - 16);
    float u = fmaf((float)(h2 >> 8), 5.9604645e-08f, -0.5f);    // [-0.5, 0.5)
    return fabsf((b + u) * 0.35172433f);                         // 1/sqrt(8+1/12)
}

__device__ __forceinline__ unsigned order_key(float v) {
    unsigned u = __float_as_uint(v);
    return (u & 0x80000000u) ? ~u : (u | 0x80000000u);
}

__device__ __forceinline__ int warp_sum(int v) {
    #pragma unroll
    for (int off = 16; off; off >>= 1) v += __shfl_xor_sync(0xffffffffu, v, off);
    return v;
}

// ---------------- K0: zero counters ----------------
__global__ __launch_bounds__(256) void k0_zero() {
    int i = blockIdx.x * 256 + threadIdx.x;
    if (i < BINS) g_phist[i] = 0;
    if (i < MAXPOS + 64) g_gapneg[i] = 0;
}

// ---------------- K1: fused perturb+transpose (cross) + interclass keys ----------------
__global__ __launch_bounds__(256) void k1_fused(
    const float* __restrict__ outp, const float* __restrict__ tgt,
    const float* __restrict__ soutp, const float* __restrict__ stgt)
{
    __shared__ float ts_tile[32][33];
    __shared__ unsigned char tb_tile[32][33];

    int tx = threadIdx.x;
    int ty = threadIdx.y;
    int c0 = blockIdx.x * 32;
    int r0 = blockIdx.y * 32;
    int cg = c0 + tx;

    #pragma unroll
    for (int j = 0; j < 4; j++) {
        int rl = ty + 8 * j;
        int row = r0 + rl;
        float sc, t;
        if (row < B_ROWS) {
            size_t o = (size_t)row * C_CLASSES + cg;
            sc = outp[o]; t = tgt[o];
        } else {
            size_t o = (size_t)(row - B_ROWS) * C_CLASSES + cg;
            sc = soutp[o]; t = stgt[o];
        }
        unsigned gi = (unsigned)(row * C_CLASSES + cg);
        float an = abs_normal(gi);
        bool pos = (t > 0.5f);
        float v = pos ? (sc - 0.01f * an) : (sc + 0.01f * an);
        ts_tile[rl][tx] = v;
        tb_tile[rl][tx] = pos ? 1 : 0;

        if (row < B_ROWS) {   // interclass stream: reuse the SAME perturbed value
            unsigned key = order_key(v);
            g_ikeys[row * C_CLASSES + cg] = key;
            unsigned pb = __ballot_sync(0xffffffffu, pos);
            if (tx == 0) g_iposbit[row * (C_CLASSES / 32) + blockIdx.x] = pb;
            if (pos) atomicAdd(&g_phist[key >> KEY_SHIFT], 1);
        }
    }
    __syncthreads();

    #pragma unroll
    for (int rep = 0; rep < 4; rep++) {
        int cl  = ty + 8 * rep;
        int cgg = c0 + cl;
        float v = ts_tile[tx][cl];
        bool  b = (tb_tile[tx][cl] != 0);
        g_tsT[(size_t)cgg * N_ROWS + r0 + tx] = v;
        unsigned wmask = __ballot_sync(0xffffffffu, b);
        if (tx == 0) g_maskT[cgg * NWORDS + blockIdx.y] = wmask;
    }
}

// ---------------- K2: per-class count-based ranking (cross term) ----------------
__global__ __launch_bounds__(256) void k2_rank()
{
    __shared__ float s_pos[8][MAXP];
    int lane = threadIdx.x & 31;
    int wid  = threadIdx.x >> 5;
    int c    = blockIdx.x * 8 + wid;

    const float4* rowp = (const float4*)(g_tsT + (size_t)c * N_ROWS);
    float4 v[10];
    #pragma unroll
    for (int i = 0; i < 10; i++) v[i] = rowp[i * 32 + lane];

    int m = 0;
    #pragma unroll
    for (int i = 0; i < 10; i++) {
        unsigned mw = g_maskT[c * NWORDS + i * 4 + (lane >> 3)];
        unsigned b4 = (mw >> ((lane & 7) * 4)) & 0xFu;
        #pragma unroll
        for (int k = 0; k < 4; k++) {
            unsigned bb = __ballot_sync(0xffffffffu, (b4 >> k) & 1u);
            float vk = (k == 0) ? v[i].x : (k == 1) ? v[i].y : (k == 2) ? v[i].z : v[i].w;
            while (bb) {
                int src = __ffs(bb) - 1;
                float pv = __shfl_sync(0xffffffffu, vk, src);
                if (lane == 0 && m < MAXP) s_pos[wid][m] = pv;
                m++;
                bb &= (bb - 1);
            }
        }
    }
    __syncwarp();
    int ms = (m < MAXP) ? m : MAXP;

    float sum = 0.0f;
    for (int kk = 0; kk < ms; kk++) {
        float p = s_pos[wid][kk];
        int cnt = 0;
        #pragma unroll
        for (int i = 0; i < 10; i++) {
            cnt += (v[i].x > p);
            cnt += (v[i].y > p);
            cnt += (v[i].z > p);
            cnt += (v[i].w > p);
        }
        int r = warp_sum(cnt) + 1;
        int s = 1;
        for (int jj = 0; jj < ms; jj++) s += (s_pos[wid][jj] > p);
        sum += (float)s / (float)r;
    }
    if (lane == 0) {
        g_prec[c]    = sum / ((float)m + 1e-5f);
        g_present[c] = (m > 0) ? 1 : 0;
    }
}

// ---------------- positive-bin scan (3 tiny kernels) ----------------
__global__ __launch_bounds__(256) void kpa_chunks() {
    int g = blockIdx.x * 256 + threadIdx.x;     // 0..NCHUNK-1
    int base = g * CHUNK;
    int s = 0;
    #pragma unroll 8
    for (int j = 0; j < CHUNK; j++) s += g_phist[base + j];
    g_pchunksum[g] = s;
}

__global__ __launch_bounds__(1024) void kpb_scan() {
    __shared__ int warp_tot[32];
    int t = threadIdx.x;
    int v0[4];
    int s = 0;
    #pragma unroll
    for (int j = 0; j < 4; j++) { v0[j] = g_pchunksum[t * 4 + j]; s += v0[j]; }
    int lane = t & 31, wid = t >> 5;
    int si = s;
    #pragma unroll
    for (int off = 1; off < 32; off <<= 1) {
        int n = __shfl_up_sync(0xffffffffu, si, off);
        if (lane >= off) si += n;
    }
    if (lane == 31) warp_tot[wid] = si;
    __syncthreads();
    if (wid == 0) {
        int w = warp_tot[lane];
        #pragma unroll
        for (int off = 1; off < 32; off <<= 1) {
            int n = __shfl_up_sync(0xffffffffu, w, off);
            if (lane >= off) w += n;
        }
        warp_tot[lane] = w;
    }
    __syncthreads();
    int base = (wid > 0 ? warp_tot[wid - 1] : 0) + si - s;
    int run = base;
    #pragma unroll
    for (int j = 0; j < 4; j++) { g_pchunksum[t * 4 + j] = run; run += v0[j]; }
    if (t == 1023) g_mtotal = run;
}

__global__ __launch_bounds__(256) void kpc_offsets() {
    int g = blockIdx.x * 256 + threadIdx.x;
    int run = g_pchunksum[g];
    int base = g * CHUNK;
    for (int j = 0; j < CHUNK; j++) {
        int h = g_phist[base + j];
        g_pexcl[base + j]   = run;
        g_pcursor[base + j] = run;
        run += h;
    }
}

// ---------------- scatter positive keys by bin ----------------
__global__ __launch_bounds__(256) void kps_scatter() {
    int w = blockIdx.x * 256 + threadIdx.x;   // 0..NPWORDS-1
    unsigned bits = g_iposbit[w];
    while (bits) {
        int bit = __ffs(bits) - 1;
        bits &= (bits - 1);
        int i = w * 32 + bit;
        unsigned key = g_ikeys[i];
        int b = key >> KEY_SHIFT;
        int d = atomicAdd(&g_pcursor[b], 1);
        g_pkeys[d] = key;
    }
}

// ---------------- KC: per-element gap counting ----------------
#define KC_THREADS (NI / 4)   // 524288
__global__ __launch_bounds__(256) void kc_gaps() {
    int tid = blockIdx.x * 256 + threadIdx.x;
    int m = g_mtotal;

    unsigned key[4]; unsigned pb[4];
    int e0[4], pc[4];
    #pragma unroll
    for (int u = 0; u < 4; u++) {
        int i = tid + u * KC_THREADS;
        key[u] = g_ikeys[i];
        pb[u]  = g_iposbit[i >> 5];       // broadcast within warp
    }
    #pragma unroll
    for (int u = 0; u < 4; u++) {
        int b = key[u] >> KEY_SHIFT;
        e0[u] = g_pexcl[b];
        pc[u] = g_phist[b];
    }
    #pragma unroll
    for (int u = 0; u < 4; u++) {
        int i = tid + u * KC_THREADS;
        int cgt = 0;
        for (int t = 0; t < pc[u]; t++) cgt += (g_pkeys[e0[u] + t] > key[u]);
        int j = (m - e0[u] - pc[u]) + cgt;   // # positives > this element
        bool pos = (pb[u] >> (i & 31)) & 1u;
        if (!pos) atomicAdd(&g_gapneg[j], 1);
    }
}

// ---------------- KS3: gap scan + interclass terms + final combine ----------------
__global__ __launch_bounds__(1024) void ks3_final(float* __restrict__ out, int out_size)
{
    __shared__ int wtot[32];
    __shared__ double wsumd[32];
    __shared__ int wsumi[32];
    int t = threadIdx.x;
    int lane = t & 31, wid = t >> 5;
    int m = g_mtotal;

    int carry = 0;
    double acc = 0.0;
    for (int base = 0; base < m; base += 1024) {
        int i = base + t;
        int g = (i < m) ? g_gapneg[i] : 0;
        int si = g;
        #pragma unroll
        for (int off = 1; off < 32; off <<= 1) {
            int n = __shfl_up_sync(0xffffffffu, si, off);
            if (lane >= off) si += n;
        }
        if (lane == 31) wtot[wid] = si;
        __syncthreads();
        if (wid == 0) {
            int w = wtot[lane];
            #pragma unroll
            for (int off = 1; off < 32; off <<= 1) {
                int n = __shfl_up_sync(0xffffffffu, w, off);
                if (lane >= off) w += n;
            }
            wtot[lane] = w;
        }
        __syncthreads();
        int P = (wid > 0 ? wtot[wid - 1] : 0) + si;
        if (i < m) {
            int r = 1 + i + carry + P;
            acc += (double)(i + 1) / (double)r;
        }
        carry += wtot[31];
        __syncthreads();
    }
    #pragma unroll
    for (int off = 16; off; off >>= 1) acc += __shfl_xor_sync(0xffffffffu, acc, off);
    if (lane == 0) wsumd[wid] = acc;
    __syncthreads();
    double isum = 0.0;
    if (t == 0) {
        #pragma unroll
        for (int i = 0; i < 32; i++) isum += wsumd[i];
    }
    __syncthreads();

    double ps = 0.0; int pr = 0;
    for (int i = t; i < C_CLASSES; i += 1024) { ps += (double)g_prec[i]; pr += g_present[i]; }
    #pragma unroll
    for (int off = 16; off; off >>= 1) {
        ps += __shfl_xor_sync(0xffffffffu, ps, off);
        pr += __shfl_xor_sync(0xffffffffu, pr, off);
    }
    if (lane == 0) { wsumd[wid] = ps; wsumi[wid] = pr; }
    __syncthreads();
    if (t == 0) {
        double pst = 0.0; int prt = 0;
        #pragma unroll
        for (int i = 0; i < 32; i++) { pst += wsumd[i]; prt += wsumi[i]; }
        int denom = (prt > 0) ? prt : 1;
        float cross = 1.0f - (float)(pst / (double)denom);
        float inter = (m > 0) ? (1.0f - (float)(isum / ((double)m + 1e-5))) : 1.0f;
        float loss = 0.5f * cross + 0.5f * inter;
        for (int j = 0; j < out_size; j++) out[j] = loss;
    }
}

// ---------------- launch ----------------
extern "C" void kernel_launch(void* const* d_in, const int* in_sizes, int n_in,
                              void* d_out, int out_size)
{
    const int SMALL = B_ROWS * C_CLASSES;
    const float* small_p[2] = {nullptr, nullptr};
    const float* big_p[2]   = {nullptr, nullptr};
    int ns = 0, nb = 0;
    for (int i = 0; i < n_in; i++) {
        if (in_sizes[i] == SMALL) { if (ns < 2) small_p[ns++] = (const float*)d_in[i]; }
        else                      { if (nb < 2) big_p[nb++]   = (const float*)d_in[i]; }
    }
    const float* outp  = small_p[0];
    const float* tgt   = small_p[1];
    const float* soutp = big_p[0];
    const float* stgt  = big_p[1];

    k0_zero<<<(BINS + 255) / 256, 256>>>();

    dim3 b1(32, 8);
    dim3 g1(C_CLASSES / 32, N_ROWS / 32);
    k1_fused<<<g1, b1>>>(outp, tgt, soutp, stgt);

    // interclass pipeline (ikeys still L2-warm)
    kpa_chunks<<<NCHUNK / 256, 256>>>();
    kpb_scan<<<1, 1024>>>();
    kpc_offsets<<<NCHUNK / 256, 256>>>();
    kps_scatter<<<NPWORDS / 256, 256>>>();
    kc_gaps<<<KC_THREADS / 256, 256>>>();

    // cross term ranking
    k2_rank<<<C_CLASSES / 8, 256>>>();

    ks3_final<<<1, 1024>>>((float*)d_out, out_size);
}